// round 5
// baseline (speedup 1.0000x reference)
#include <cuda_runtime.h>

// Problem constants (from reference)
#define NPTS   4096
#define BATCH  (1 << 20)
#define NNODE  4096
#define PLANE  (NNODE * NNODE)        // 16777216
#define TAU_MAX 10.0f

// LUTs: f_i(t) for t in [-1.0, 0.1] (x/dt MLP), g_i(t) for t in [0, 1] (y MLP).
// 4 basis values packed per point. (NPTS+1) points, ~64KB each -> L1 resident.
__device__ float4 g_tabX[NPTS + 1];
__device__ float4 g_tabY[NPTS + 1];

// softplus(100 z)/100, numerically stable, matches jax.nn.softplus to fp32.
__device__ __forceinline__ float sp100(float z) {
    float u = 100.0f * z;
    float r = fmaxf(u, 0.0f);
    float e = __expf(-fabsf(u));           // underflows to 0 for |u| large -> exact
    return (r + __logf(1.0f + e)) * 0.01f;
}

// Build both LUTs. One thread per (table, point); each computes all 4 bases.
__global__ void build_tables_kernel(
    const float* __restrict__ Wx1, const float* __restrict__ Wx2, const float* __restrict__ Wx3,
    const float* __restrict__ Wy1, const float* __restrict__ Wy2, const float* __restrict__ Wy3,
    const float* __restrict__ bx1, const float* __restrict__ bx2, const float* __restrict__ bx3,
    const float* __restrict__ by1, const float* __restrict__ by2, const float* __restrict__ by3)
{
    int tid = blockIdx.x * blockDim.x + threadIdx.x;
    if (tid >= 2 * (NPTS + 1)) return;
    bool isY = (tid >= (NPTS + 1));
    int  i   = isY ? tid - (NPTS + 1) : tid;
    float t  = isY ? (float)i * (1.0f / NPTS)
                   : (-1.0f + (float)i * (1.1f / NPTS));

    const float* W1 = isY ? Wy1 : Wx1;
    const float* W2 = isY ? Wy2 : Wx2;
    const float* W3 = isY ? Wy3 : Wx3;
    const float* b1 = isY ? by1 : bx1;
    const float* b2 = isY ? by2 : bx2;
    const float* b3 = isY ? by3 : bx3;

    float o[4];
#pragma unroll
    for (int n = 0; n < 4; n++) {
        float h1[5];
#pragma unroll
        for (int w = 0; w < 5; w++)
            h1[w] = sp100(fmaf(t, __ldg(&W1[n * 5 + w]), __ldg(&b1[n * 5 + w])));
        float h2[5];
#pragma unroll
        for (int v = 0; v < 5; v++) {
            float z = __ldg(&b2[n * 5 + v]);
#pragma unroll
            for (int w = 0; w < 5; w++)
                z = fmaf(h1[w], __ldg(&W2[n * 25 + w * 5 + v]), z);
            h2[v] = sp100(z);
        }
        float z = __ldg(&b3[n]);
#pragma unroll
        for (int w = 0; w < 5; w++)
            z = fmaf(h2[w], __ldg(&W3[n * 5 + w]), z);
        o[n] = z;
    }
    float4 r = make_float4(o[0], o[1], o[2], o[3]);
    if (isY) g_tabY[i] = r; else g_tabX[i] = r;
}

// Main kernel: per sample, 2 LUT interps + 4x4 GEMV + 4 random gathers from B.
__global__ void __launch_bounds__(256)
eval_kernel(const float2* __restrict__ x, const float2* __restrict__ y,
            const float* __restrict__ B, const float* __restrict__ W,
            float* __restrict__ out)
{
    int b = blockIdx.x * blockDim.x + threadIdx.x;
    if (b >= BATCH) return;

    float2 xv = __ldcs(&x[b]);   // (tx, xi_as_float)
    float2 yv = __ldcs(&y[b]);   // (ty, yi_as_float)
    float dt = xv.x - yv.x;

    float res = 0.0f;
    if (dt <= TAU_MAX) {
        // x-table lookup: u = dt/100 in (-1, 0.1]
        float px = fmaf(dt, 0.01f, 1.0f) * ((float)NPTS / 1.1f);
        px = fminf(fmaxf(px, 0.0f), (float)NPTS);
        int   ix = min((int)px, NPTS - 1);
        float fx = px - (float)ix;
        float4 a0 = __ldg(&g_tabX[ix]);
        float4 a1 = __ldg(&g_tabX[ix + 1]);

        // y-table lookup: v = ty/100 in [0, 1)
        float py = yv.x * (0.01f * (float)NPTS);
        py = fminf(fmaxf(py, 0.0f), (float)NPTS);
        int   iy = min((int)py, NPTS - 1);
        float fy = py - (float)iy;
        float4 c0 = __ldg(&g_tabY[iy]);
        float4 c1 = __ldg(&g_tabY[iy + 1]);

        float f0 = fmaf(fx, a1.x - a0.x, a0.x);
        float f1 = fmaf(fx, a1.y - a0.y, a0.y);
        float f2 = fmaf(fx, a1.z - a0.z, a0.z);
        float f3 = fmaf(fx, a1.w - a0.w, a0.w);
        float g0 = fmaf(fy, c1.x - c0.x, c0.x);
        float g1 = fmaf(fy, c1.y - c0.y, c0.y);
        float g2 = fmaf(fy, c1.z - c0.z, c0.z);
        float g3 = fmaf(fy, c1.w - c0.w, c0.w);

        float k0 = f0 * g0, k1 = f1 * g1, k2 = f2 * g2, k3 = f3 * g3;

        // c_j = sum_i k_i * W[i][j];  W rows are float4 over j
        const float4* W4 = (const float4*)W;
        float4 w0 = __ldg(&W4[0]);
        float4 w1 = __ldg(&W4[1]);
        float4 w2 = __ldg(&W4[2]);
        float4 w3 = __ldg(&W4[3]);
        float cj0 = fmaf(k3, w3.x, fmaf(k2, w2.x, fmaf(k1, w1.x, k0 * w0.x)));
        float cj1 = fmaf(k3, w3.y, fmaf(k2, w2.y, fmaf(k1, w1.y, k0 * w0.y)));
        float cj2 = fmaf(k3, w3.z, fmaf(k2, w2.z, fmaf(k1, w1.z, k0 * w0.z)));
        float cj3 = fmaf(k3, w3.w, fmaf(k2, w2.w, fmaf(k1, w1.w, k0 * w0.w)));

        // 4 random gathers: B[j, yi, xi]
        int xi = (int)xv.y;
        int yi = (int)yv.y;
        const float* Bp = B + (yi * NNODE + xi);
        float v0 = __ldcs(Bp);
        float v1 = __ldcs(Bp + PLANE);
        float v2 = __ldcs(Bp + 2 * PLANE);
        float v3 = __ldcs(Bp + 3 * PLANE);

        res = fmaf(cj3, v3, fmaf(cj2, v2, fmaf(cj1, v1, cj0 * v0)));
    }
    out[b] = res;
}

extern "C" void kernel_launch(void* const* d_in, const int* in_sizes, int n_in,
                              void* d_out, int out_size)
{
    const float* x   = (const float*)d_in[0];
    const float* y   = (const float*)d_in[1];
    const float* B   = (const float*)d_in[2];
    const float* Wx1 = (const float*)d_in[3];
    const float* Wx2 = (const float*)d_in[4];
    const float* Wx3 = (const float*)d_in[5];
    const float* Wy1 = (const float*)d_in[6];
    const float* Wy2 = (const float*)d_in[7];
    const float* Wy3 = (const float*)d_in[8];
    const float* bx1 = (const float*)d_in[9];
    const float* bx2 = (const float*)d_in[10];
    const float* bx3 = (const float*)d_in[11];
    const float* by1 = (const float*)d_in[12];
    const float* by2 = (const float*)d_in[13];
    const float* by3 = (const float*)d_in[14];
    const float* W   = (const float*)d_in[15];

    int build_threads = 2 * (NPTS + 1);
    build_tables_kernel<<<(build_threads + 255) / 256, 256>>>(
        Wx1, Wx2, Wx3, Wy1, Wy2, Wy3, bx1, bx2, bx3, by1, by2, by3);

    eval_kernel<<<BATCH / 256, 256>>>(
        (const float2*)x, (const float2*)y, B, W, (float*)d_out);
}